// round 14
// baseline (speedup 1.0000x reference)
#include <cuda_runtime.h>
#include <cuda_bf16.h>

#define D        512
#define NTAU     100
#define HSLOTS   128                 // rings: >= NTAU + 27 margin, power of 2
#define XCTAS    8                   // cluster of 8 x-CTAs owns all 512 rows
#define YCTAS    8                   // 8 y-CTAs compute W2·y 100 steps behind
#define WARPS    16
#define RPW      4                   // rows per warp
#define THREADS  512

// Global tagged rings: word = {hi32: tag = step+1, lo32: float}.
__device__ unsigned long long g_xring[HSLOTS * D];  // x history (for y-CTAs)
__device__ unsigned long long g_yacc [HSLOTS * D];  // reduced W2·y_j per row

__device__ __forceinline__ unsigned long long make_tw(unsigned tag, float x) {
    return ((unsigned long long)tag << 32) | (unsigned long long)__float_as_uint(x);
}
__device__ __forceinline__ unsigned long long ld_g(const unsigned long long* p) {
    unsigned long long v;
    asm volatile("ld.relaxed.gpu.global.b64 %0, [%1];" : "=l"(v) : "l"(p) : "memory");
    return v;
}
__device__ __forceinline__ void st_g(unsigned long long* p, unsigned long long v) {
    asm volatile("st.relaxed.gpu.global.b64 [%0], %1;" :: "l"(p), "l"(v) : "memory");
}
// DSMEM: tagged word ops at cluster scope (single-copy atomic, tearing-proof).
__device__ __forceinline__ unsigned long long ld_s(unsigned a) {
    unsigned long long v;
    asm volatile("ld.relaxed.cluster.shared.b64 %0, [%1];" : "=l"(v) : "r"(a) : "memory");
    return v;
}
__device__ __forceinline__ void st_srem(unsigned a, unsigned long long v) {
    asm volatile("st.relaxed.cluster.shared::cluster.b64 [%0], %1;" :: "r"(a), "l"(v) : "memory");
}
__device__ __forceinline__ unsigned mapa_u32(unsigned a, unsigned rank) {
    unsigned r;
    asm volatile("mapa.shared::cluster.u32 %0, %1, %2;" : "=r"(r) : "r"(a), "r"(rank));
    return r;
}
#define CLUSTER_SYNC() do { \
    asm volatile("barrier.cluster.arrive.aligned;" ::: "memory"); \
    asm volatile("barrier.cluster.wait.aligned;"  ::: "memory"); } while (0)

// fast tanh: 1 - 2/(exp(2z)+1); saturations exact (proven R12).
__device__ __forceinline__ float tanh_fast(float z) {
    const float e = __expf(2.0f * z);
    return 1.0f - __fdividef(2.0f, e + 1.0f);
}

__global__ void reset_kernel() {     // <<<512, 256>>> = 131072 = 2 * HSLOTS * D
    const int i = blockIdx.x * 256 + threadIdx.x;
    if (i < HSLOTS * D) g_xring[i] = 0ULL;
    else                g_yacc[i - HSLOTS * D] = 0ULL;
}

__global__ void __launch_bounds__(THREADS, 1) __cluster_dims__(XCTAS, 1, 1)
ndde_kernel(const float* __restrict__ x0,  const float* __restrict__ tau,
            const float* __restrict__ W1,  const float* __restrict__ W2,
            const float* __restrict__ b,   float* __restrict__ out, int N)
{
    __shared__ __align__(16) unsigned long long tile[2][D];  // x_j tiles (8 KB)

    const int  lane = threadIdx.x & 31;
    const int  warp = threadIdx.x >> 5;
    const long NP1  = (long)N + 1;

    if (blockIdx.x < XCTAS) {
        // ================= X-CTAs (cluster): own 64 rows each =================
        const int base  = blockIdx.x * (WARPS * RPW) + warp * RPW;
        const int r     = lane >> 3;          // my row within the warp (0..3)
        const int c     = lane & 7;           // my destination peer CTA (0..7)
        const int myrow = base + r;

        for (int i = threadIdx.x; i < 2 * D; i += THREADS)
            ((unsigned long long*)tile)[i] = 0ULL;       // tags start invalid
        CLUSTER_SYNC();                                   // tiles ready cluster-wide

        // remote tile word address for (peer c, row myrow), parity 0
        const unsigned lt0   = (unsigned)__cvta_generic_to_shared(&tile[0][0]);
        const unsigned peer0 = mapa_u32(lt0, (unsigned)c) + (unsigned)myrow * 8u;

        const float dt  = 0.01f * __ldg(tau);
        const float b_r = __ldg(b + myrow);
        float xcur = __ldg(x0 + myrow);

        // publish x_0 to every peer tile (parity 0, tag 1) + global ring + out
        st_srem(peer0, make_tw(1u, xcur));
        if (c == 0) {
            st_g(&g_xring[myrow], make_tw(1u, xcur));
            out[(long)myrow * NP1] = xcur;
        }

        float w1r[RPW][16];                  // W1 rows in registers
        #pragma unroll
        for (int rr = 0; rr < RPW; ++rr)
            #pragma unroll
            for (int i = 0; i < 16; ++i)
                w1r[rr][i] = W1[(long)(base + rr) * D + lane + 32 * i];

        for (int j = 0; j < N; ++j) {
            const unsigned need = (unsigned)(j + 1);

            // prefetch this row's W2·y_j scalar (tagged) — checked after x work
            const unsigned long long* yap =
                &g_yacc[(size_t)(j & (HSLOTS - 1)) * D + myrow];
            unsigned long long ya = ld_g(yap);

            // spin on LOCAL tile words (parallel retry, LDS latency)
            const unsigned tb = lt0 + (unsigned)(j & 1) * (D * 8);
            unsigned long long v[16];
            unsigned stale = 0xFFFFu;
            do {
                #pragma unroll
                for (int i = 0; i < 16; ++i)
                    if (stale & (1u << i))
                        v[i] = ld_s(tb + (unsigned)(lane + 32 * i) * 8u);
                #pragma unroll
                for (int i = 0; i < 16; ++i)
                    if ((stale & (1u << i)) && (unsigned)(v[i] >> 32) >= need)
                        stale &= ~(1u << i);
            } while (stale);

            // 4 rows × 16 FMA (independent chains), then 4 butterfly reduces
            float a0 = 0.f, a1 = 0.f, a2 = 0.f, a3 = 0.f;
            #pragma unroll
            for (int i = 0; i < 16; ++i) {
                const float xv = __uint_as_float((unsigned)v[i]);
                a0 = fmaf(w1r[0][i], xv, a0);
                a1 = fmaf(w1r[1][i], xv, a1);
                a2 = fmaf(w1r[2][i], xv, a2);
                a3 = fmaf(w1r[3][i], xv, a3);
            }
            #pragma unroll
            for (int off = 16; off; off >>= 1) {
                a0 += __shfl_xor_sync(0xffffffffu, a0, off);
                a1 += __shfl_xor_sync(0xffffffffu, a1, off);
                a2 += __shfl_xor_sync(0xffffffffu, a2, off);
                a3 += __shfl_xor_sync(0xffffffffu, a3, off);
            }
            while ((unsigned)(ya >> 32) < need) ya = ld_g(yap);  // ~never spins

            const float s = (r & 2) ? ((r & 1) ? a3 : a2)
                                    : ((r & 1) ? a1 : a0);
            const float z = s + __uint_as_float((unsigned)ya) + b_r;
            xcur = fmaf(dt, tanh_fast(z), xcur);

            // publish x_{j+1}: DSMEM to all peers + (lane c==0) global ring + out
            const unsigned long long pub = make_tw((unsigned)(j + 2), xcur);
            st_srem(peer0 + (unsigned)((j + 1) & 1) * (D * 8), pub);
            if (c == 0) {
                st_g(&g_xring[(size_t)((j + 1) & (HSLOTS - 1)) * D + myrow], pub);
                out[(long)myrow * NP1 + (j + 1)] = xcur;
            }
        }

        // EXIT HAZARD FIX (R13 fault): no CTA may retire while peer DSMEM
        // stores can still target its SMEM. arrive has release semantics for
        // prior shared::cluster stores, so after wait all stores have landed.
        CLUSTER_SYNC();
        return;
    }

    // ================= Y-CTAs: W2·y engine, 100 steps behind =================
    {
        const int base  = (blockIdx.x - XCTAS) * (WARPS * RPW) + warp * RPW;
        const int r     = lane >> 3;
        const int c     = lane & 7;
        const int myrow = base + r;

        float w2r[RPW][16];
        #pragma unroll
        for (int rr = 0; rr < RPW; ++rr)
            #pragma unroll
            for (int i = 0; i < 16; ++i)
                w2r[rr][i] = W2[(long)(base + rr) * D + lane + 32 * i];

        // constant W2·x0 (y_j = x_0 for j < NTAU), reduced once
        float c0 = 0.f, c1 = 0.f, c2 = 0.f, c3 = 0.f;
        #pragma unroll
        for (int i = 0; i < 16; ++i) {
            const float xv = __ldg(x0 + lane + 32 * i);
            c0 = fmaf(w2r[0][i], xv, c0);
            c1 = fmaf(w2r[1][i], xv, c1);
            c2 = fmaf(w2r[2][i], xv, c2);
            c3 = fmaf(w2r[3][i], xv, c3);
        }
        #pragma unroll
        for (int off = 16; off; off >>= 1) {
            c0 += __shfl_xor_sync(0xffffffffu, c0, off);
            c1 += __shfl_xor_sync(0xffffffffu, c1, off);
            c2 += __shfl_xor_sync(0xffffffffu, c2, off);
            c3 += __shfl_xor_sync(0xffffffffu, c3, off);
        }

        for (int jn = 0; jn < N; ++jn) {
            float s0 = c0, s1 = c1, s2 = c2, s3 = c3;
            if (jn >= NTAU) {
                const unsigned long long* xs =
                    &g_xring[(size_t)((jn - NTAU) & (HSLOTS - 1)) * D];
                const unsigned need = (unsigned)(jn - NTAU + 1);
                unsigned long long v[16];
                unsigned stale = 0xFFFFu;
                do {                                      // parallel retry
                    #pragma unroll
                    for (int i = 0; i < 16; ++i)
                        if (stale & (1u << i))
                            v[i] = ld_g(xs + lane + 32 * i);
                    #pragma unroll
                    for (int i = 0; i < 16; ++i)
                        if ((stale & (1u << i)) && (unsigned)(v[i] >> 32) >= need)
                            stale &= ~(1u << i);
                } while (stale);
                s0 = s1 = s2 = s3 = 0.f;
                #pragma unroll
                for (int i = 0; i < 16; ++i) {
                    const float yv = __uint_as_float((unsigned)v[i]);
                    s0 = fmaf(w2r[0][i], yv, s0);
                    s1 = fmaf(w2r[1][i], yv, s1);
                    s2 = fmaf(w2r[2][i], yv, s2);
                    s3 = fmaf(w2r[3][i], yv, s3);
                }
                #pragma unroll
                for (int off = 16; off; off >>= 1) {
                    s0 += __shfl_xor_sync(0xffffffffu, s0, off);
                    s1 += __shfl_xor_sync(0xffffffffu, s1, off);
                    s2 += __shfl_xor_sync(0xffffffffu, s2, off);
                    s3 += __shfl_xor_sync(0xffffffffu, s3, off);
                }
            }
            if (c == 0) {
                const float s = (r & 2) ? ((r & 1) ? s3 : s2)
                                        : ((r & 1) ? s1 : s0);
                st_g(&g_yacc[(size_t)(jn & (HSLOTS - 1)) * D + myrow],
                     make_tw((unsigned)(jn + 1), s));
            }
        }
    }
}

extern "C" void kernel_launch(void* const* d_in, const int* in_sizes, int n_in,
                              void* d_out, int out_size) {
    const float* x0  = (const float*)d_in[0];
    const float* tau = (const float*)d_in[1];
    const float* W1  = (const float*)d_in[2];
    const float* W2  = (const float*)d_in[3];
    const float* b   = (const float*)d_in[4];
    float* out = (float*)d_out;

    const int N = out_size / D - 1;    // out is [D, N+1]

    reset_kernel<<<512, 256>>>();      // zero rings (graph-replay determinism)
    ndde_kernel<<<XCTAS + YCTAS, THREADS>>>(x0, tau, W1, W2, b, out, N);
}

// round 15
// speedup vs baseline: 2.6109x; 2.6109x over previous
#include <cuda_runtime.h>
#include <cuda_bf16.h>

#define D        512
#define NTAU     100
#define HSLOTS   128                 // rings: tag-gated, >=27-step overwrite margin
#define XCTAS    32
#define YCTAS    32
#define WARPS    16                  // compute warps per CTA (1 row each)
#define THREADS  ((WARPS + 1) * 32)  // 544: 16 compute + 1 poller warp

// Tagged words: {hi32: tag = step+1, lo32: float}. Relaxed-atomic b64 =>
// single-copy atomic (tearing-proof; proven R6..R12).
__device__ unsigned long long g_tag [HSLOTS * D];   // x history ring
__device__ unsigned long long g_yacc[HSLOTS * D];   // reduced W2·y_j per row

__device__ __forceinline__ unsigned long long make_tw(unsigned tag, float x) {
    return ((unsigned long long)tag << 32) | (unsigned long long)__float_as_uint(x);
}
__device__ __forceinline__ unsigned long long ld_g(const unsigned long long* p) {
    unsigned long long v;
    asm volatile("ld.relaxed.gpu.global.b64 %0, [%1];" : "=l"(v) : "l"(p) : "memory");
    return v;
}
__device__ __forceinline__ void st_g(unsigned long long* p, unsigned long long v) {
    asm volatile("st.relaxed.gpu.global.b64 [%0], %1;" :: "l"(p), "l"(v) : "memory");
}

// x-CTAs: poller arrives (never waits), compute syncs — R12 proven pattern.
#define TILE_ARRIVE() asm volatile("bar.arrive 1, %0;" :: "n"(THREADS) : "memory")
#define TILE_WAIT()   asm volatile("bar.sync   1, %0;" :: "n"(THREADS) : "memory")
// y-CTAs: FULL barrier both sides (poller gather is never backpressured by
// local consumption — x runs ~100 steps ahead — so arrive-only would overrun).
#define YBAR()        asm volatile("bar.sync   2, %0;" :: "n"(THREADS) : "memory")

// fast tanh: 1 - 2/(exp(2z)+1); saturations exact (proven R12).
__device__ __forceinline__ float tanh_fast(float z) {
    const float e = __expf(2.0f * z);
    return 1.0f - __fdividef(2.0f, e + 1.0f);
}

__global__ void reset_kernel() {     // <<<512, 256>>> = 2 * HSLOTS * D words
    const int i = blockIdx.x * 256 + threadIdx.x;
    if (i < HSLOTS * D) g_tag[i] = 0ULL;
    else                g_yacc[i - HSLOTS * D] = 0ULL;
}

__global__ void __launch_bounds__(THREADS, 1) ndde_kernel(
    const float* __restrict__ x0,  const float* __restrict__ tau,
    const float* __restrict__ W1,  const float* __restrict__ W2,
    const float* __restrict__ b,   float* __restrict__ out, int N)
{
    __shared__ __align__(16) float sx[2][D];   // double-buffered tile

    const int  lane = threadIdx.x & 31;
    const int  warp = threadIdx.x >> 5;
    const long NP1  = (long)N + 1;

    if (blockIdx.x < XCTAS) {
        // ======================= X-CTAs =======================
        if (warp == WARPS) {
            // ---- poller: gather x_j tile, parallel retry (R12 proven) ----
            for (int j = 0; j < N; ++j) {
                const unsigned long long* xs =
                    &g_tag[(size_t)(j & (HSLOTS - 1)) * D];
                const unsigned need = (unsigned)(j + 1);
                unsigned long long v[16];
                unsigned stale = 0xFFFFu;
                do {
                    #pragma unroll
                    for (int i = 0; i < 16; ++i)
                        if (stale & (1u << i))
                            v[i] = ld_g(xs + lane + 32 * i);
                    #pragma unroll
                    for (int i = 0; i < 16; ++i)
                        if ((stale & (1u << i)) && (unsigned)(v[i] >> 32) >= need)
                            stale &= ~(1u << i);
                } while (stale);
                #pragma unroll
                for (int i = 0; i < 16; ++i)
                    sx[j & 1][lane + 32 * i] = __uint_as_float((unsigned)v[i]);
                TILE_ARRIVE();
            }
            return;
        }
        // ---- compute warp: one row ----
        const int row = blockIdx.x * WARPS + warp;
        float xcur = __ldg(x0 + row);
        if (lane == 0) {
            st_g(&g_tag[row], make_tw(1u, xcur));   // x_0, tag 1
            out[(long)row * NP1] = xcur;
        }
        float4 w1q[4];                               // k = 128g + 4*lane + c
        const float4* W1v = (const float4*)(W1 + (long)row * D);
        #pragma unroll
        for (int g = 0; g < 4; ++g) w1q[g] = __ldg(W1v + g * 32 + lane);
        const float dt  = 0.01f * __ldg(tau);
        const float b_r = __ldg(b + row);

        for (int j = 0; j < N; ++j) {
            // prefetch this row's reduced W2·y_j (latency hidden by TILE_WAIT)
            const unsigned long long* yap =
                &g_yacc[(size_t)(j & (HSLOTS - 1)) * D + row];
            unsigned long long ya = 0ULL;
            if (lane == 0) ya = ld_g(yap);

            TILE_WAIT();                             // tile j ready

            const float4* xv = (const float4*)sx[j & 1];
            float4 xq[4];
            #pragma unroll
            for (int g = 0; g < 4; ++g) xq[g] = xv[g * 32 + lane];
            float a0 = 0.f, a1 = 0.f;
            #pragma unroll
            for (int g = 0; g < 4; ++g) {
                a0 = fmaf(w1q[g].x, xq[g].x, a0);
                a1 = fmaf(w1q[g].y, xq[g].y, a1);
                a0 = fmaf(w1q[g].z, xq[g].z, a0);
                a1 = fmaf(w1q[g].w, xq[g].w, a1);
            }
            float acc = a0 + a1;
            #pragma unroll
            for (int off = 16; off; off >>= 1)
                acc += __shfl_xor_sync(0xffffffffu, acc, off);

            if (lane == 0) {
                while ((unsigned)(ya >> 32) < (unsigned)(j + 1))
                    ya = ld_g(yap);                  // ~never spins steady-state
                const float z = acc + __uint_as_float((unsigned)ya) + b_r;
                xcur = fmaf(dt, tanh_fast(z), xcur);
                st_g(&g_tag[(size_t)((j + 1) & (HSLOTS - 1)) * D + row],
                     make_tw((unsigned)(j + 2), xcur));
                out[(long)row * NP1 + (j + 1)] = xcur;
            }
        }
        return;
    }

    // ======================= Y-CTAs (trail 100 steps) =======================
    const int ysteady = (N > NTAU) ? (N - NTAU) : 0;   // # of gathered steps
    if (warp == WARPS) {
        // ---- y poller: gather x_{jn-NTAU} tiles (no spin in steady state) ----
        for (int t = 0; t < ysteady; ++t) {
            const int jn = NTAU + t;
            const unsigned long long* xs =
                &g_tag[(size_t)((jn - NTAU) & (HSLOTS - 1)) * D];
            const unsigned need = (unsigned)(jn - NTAU + 1);
            unsigned long long v[16];
            unsigned stale = 0xFFFFu;
            do {
                #pragma unroll
                for (int i = 0; i < 16; ++i)
                    if (stale & (1u << i))
                        v[i] = ld_g(xs + lane + 32 * i);
                #pragma unroll
                for (int i = 0; i < 16; ++i)
                    if ((stale & (1u << i)) && (unsigned)(v[i] >> 32) >= need)
                        stale &= ~(1u << i);
            } while (stale);
            #pragma unroll
            for (int i = 0; i < 16; ++i)
                sx[jn & 1][lane + 32 * i] = __uint_as_float((unsigned)v[i]);
            YBAR();                                  // full bar: paced by compute
        }
        return;
    }
    // ---- y compute warp: one row ----
    {
        const int row = (blockIdx.x - XCTAS) * WARPS + warp;
        float4 w2q[4];
        const float4* W2v = (const float4*)(W2 + (long)row * D);
        #pragma unroll
        for (int g = 0; g < 4; ++g) w2q[g] = __ldg(W2v + g * 32 + lane);

        // constant W2·x0 for jn < NTAU, published immediately (unblocks x j=0)
        const float4* X0v = (const float4*)x0;
        float a0 = 0.f, a1 = 0.f;
        #pragma unroll
        for (int g = 0; g < 4; ++g) {
            const float4 xq = __ldg(X0v + g * 32 + lane);
            a0 = fmaf(w2q[g].x, xq.x, a0);
            a1 = fmaf(w2q[g].y, xq.y, a1);
            a0 = fmaf(w2q[g].z, xq.z, a0);
            a1 = fmaf(w2q[g].w, xq.w, a1);
        }
        float sc = a0 + a1;
        #pragma unroll
        for (int off = 16; off; off >>= 1)
            sc += __shfl_xor_sync(0xffffffffu, sc, off);
        if (lane == 0) {
            const int lim = (N < NTAU) ? N : NTAU;
            for (int jn = 0; jn < lim; ++jn)
                st_g(&g_yacc[(size_t)(jn & (HSLOTS - 1)) * D + row],
                     make_tw((unsigned)(jn + 1), sc));
        }

        for (int t = 0; t < ysteady; ++t) {
            const int jn = NTAU + t;
            YBAR();                                  // tile jn ready
            const float4* yv = (const float4*)sx[jn & 1];
            float s0 = 0.f, s1 = 0.f;
            #pragma unroll
            for (int g = 0; g < 4; ++g) {
                const float4 yq = yv[g * 32 + lane];
                s0 = fmaf(w2q[g].x, yq.x, s0);
                s1 = fmaf(w2q[g].y, yq.y, s1);
                s0 = fmaf(w2q[g].z, yq.z, s0);
                s1 = fmaf(w2q[g].w, yq.w, s1);
            }
            float s = s0 + s1;
            #pragma unroll
            for (int off = 16; off; off >>= 1)
                s += __shfl_xor_sync(0xffffffffu, s, off);
            if (lane == 0)
                st_g(&g_yacc[(size_t)(jn & (HSLOTS - 1)) * D + row],
                     make_tw((unsigned)(jn + 1), s));
        }
    }
}

extern "C" void kernel_launch(void* const* d_in, const int* in_sizes, int n_in,
                              void* d_out, int out_size) {
    const float* x0  = (const float*)d_in[0];
    const float* tau = (const float*)d_in[1];
    const float* W1  = (const float*)d_in[2];
    const float* W2  = (const float*)d_in[3];
    const float* b   = (const float*)d_in[4];
    float* out = (float*)d_out;

    const int N = out_size / D - 1;    // out is [D, N+1]

    reset_kernel<<<512, 256>>>();      // zero rings (graph-replay determinism)
    ndde_kernel<<<XCTAS + YCTAS, THREADS>>>(x0, tau, W1, W2, b, out, N);
}